// round 4
// baseline (speedup 1.0000x reference)
#include <cuda_runtime.h>
#include <cstdint>

#define CIN  10
#define C    64
#define SMAX 30001
#define EPS  1e-3f
#define FULLMASK 0xffffffffu

// ---------------- device scratch (no allocations allowed) ----------------
__device__ float g_m1[CIN];        // sum of inputs per feature
__device__ float g_m2[55];         // upper-tri second moments sum_{n} v_j v_k
__device__ float g_Wf[C * CIN];    // BN-folded linear weights
__device__ float g_bias[C];        // BN-folded bias
__device__ float g_gsum[C];        // sum over points of relu(bn(linear))
__device__ float g_xg[C];          // global-branch additive term
__device__ int   g_segstart[SMAX]; // pillar start offsets (+ sentinel)

__device__ __forceinline__ float sigmoidf_fast(float z) {
    return __fdividef(1.0f, 1.0f + __expf(-z));
}

__device__ __forceinline__ float warp_sum(float v) {
#pragma unroll
    for (int o = 16; o > 0; o >>= 1) v += __shfl_down_sync(FULLMASK, v, o);
    return v;
}

// ---------------- K0: zero accumulators ----------------
__global__ void k_zero() {
    int t = threadIdx.x;
    if (t < CIN) g_m1[t] = 0.0f;
    if (t < 55)  g_m2[t] = 0.0f;
    if (t < C)   g_gsum[t] = 0.0f;
}

// ---------------- K1: segment boundaries (unq_inv is sorted) ----------------
__global__ void k_bounds(const int* __restrict__ unq, int n, int s_count) {
    int i = blockIdx.x * blockDim.x + threadIdx.x;
    if (i >= n) return;
    int cur = unq[i];
    if (i == 0) {
        for (int t = 0; t <= cur; t++) g_segstart[t] = 0;
    } else {
        int prev = unq[i - 1];
        for (int t = prev + 1; t <= cur; t++) g_segstart[t] = i;
    }
    if (i == n - 1) {
        for (int t = cur + 1; t <= s_count; t++) g_segstart[t] = n;
    }
}

// ---------------- K2: input first/second moments ----------------
__global__ void k_moments(const float* __restrict__ inp, int n) {
    float a1[CIN];
    float a2[55];
#pragma unroll
    for (int k = 0; k < CIN; k++) a1[k] = 0.0f;
#pragma unroll
    for (int k = 0; k < 55; k++) a2[k] = 0.0f;

    int stride = gridDim.x * blockDim.x;
    for (int i = blockIdx.x * blockDim.x + threadIdx.x; i < n; i += stride) {
        const float* row = inp + (size_t)i * CIN;
        float v[CIN];
#pragma unroll
        for (int k = 0; k < CIN; k++) v[k] = __ldg(row + k);
        int t = 0;
#pragma unroll
        for (int j = 0; j < CIN; j++) {
            a1[j] += v[j];
#pragma unroll
            for (int k = j; k < CIN; k++) { a2[t] += v[j] * v[k]; t++; }
        }
    }

    int lane = threadIdx.x & 31;
#pragma unroll
    for (int j = 0; j < CIN; j++) {
        float r = warp_sum(a1[j]);
        if (lane == 0) atomicAdd(&g_m1[j], r);
    }
#pragma unroll
    for (int t = 0; t < 55; t++) {
        float r = warp_sum(a2[t]);
        if (lane == 0) atomicAdd(&g_m2[t], r);
    }
}

// ---------------- K3: fold BN into linear ----------------
__global__ void k_fold(const float* __restrict__ W, const float* __restrict__ gamma,
                       const float* __restrict__ beta, int n) {
    int c = threadIdx.x;
    if (c >= C) return;
    float invn = 1.0f / (float)n;
    float wr[CIN];
#pragma unroll
    for (int k = 0; k < CIN; k++) wr[k] = W[c * CIN + k];

    float mu = 0.0f;
#pragma unroll
    for (int k = 0; k < CIN; k++) mu += wr[k] * g_m1[k];
    mu *= invn;

    float ex2 = 0.0f;
    int t = 0;
#pragma unroll
    for (int j = 0; j < CIN; j++) {
#pragma unroll
        for (int k = j; k < CIN; k++) {
            float f = wr[j] * wr[k] * g_m2[t];
            ex2 += (k == j) ? f : 2.0f * f;
            t++;
        }
    }
    ex2 *= invn;
    float var = ex2 - mu * mu;
    float alpha = gamma[c] * rsqrtf(var + EPS);
    g_bias[c] = beta[c] - mu * alpha;
#pragma unroll
    for (int k = 0; k < CIN; k++) g_Wf[c * CIN + k] = alpha * wr[k];
}

// ---------------- K4: accumulate g = sum over points of relu(x) ----------------
__global__ void k_gpass(const float* __restrict__ inp, int n) {
    __shared__ float sWf[C * CIN];
    __shared__ float sB[C];
    for (int t = threadIdx.x; t < C * CIN; t += blockDim.x) sWf[t] = g_Wf[t];
    for (int t = threadIdx.x; t < C; t += blockDim.x) sB[t] = g_bias[t];
    __syncthreads();

    float acc[C];
#pragma unroll
    for (int c = 0; c < C; c++) acc[c] = 0.0f;

    int stride = gridDim.x * blockDim.x;
    for (int i = blockIdx.x * blockDim.x + threadIdx.x; i < n; i += stride) {
        const float* row = inp + (size_t)i * CIN;
        float v[CIN];
#pragma unroll
        for (int k = 0; k < CIN; k++) v[k] = __ldg(row + k);
#pragma unroll
        for (int c = 0; c < C; c++) {
            float x = sB[c];
#pragma unroll
            for (int k = 0; k < CIN; k++) x += sWf[c * CIN + k] * v[k];
            acc[c] += fmaxf(x, 0.0f);
        }
    }

    int lane = threadIdx.x & 31;
#pragma unroll
    for (int c = 0; c < C; c++) {
        float r = warp_sum(acc[c]);
        if (lane == 0) atomicAdd(&g_gsum[c], r);
    }
}

// ---------------- K5: global branch xg = pw2 @ relu(dw2 * mean(x)) ----------------
__global__ void k_xg(const float* __restrict__ dw2, const float* __restrict__ pw2, int n) {
    __shared__ float t[C];
    int c = threadIdx.x;
    if (c < C) t[c] = fmaxf(dw2[c] * (g_gsum[c] / (float)n), 0.0f);
    __syncthreads();
    if (c >= C) return;
    float acc = 0.0f;
#pragma unroll
    for (int k = 0; k < C; k++) acc += pw2[c * C + k] * t[k];
    g_xg[c] = acc;
}

// ---------------- K6: main fused pass, warp-per-pillar ----------------
__global__ __launch_bounds__(256) void k_main(const float* __restrict__ inp,
                                              const float* __restrict__ pw1,
                                              const float* __restrict__ dw1,
                                              float* __restrict__ out,
                                              int s_count) {
    __shared__ float sWf[C * CIN];
    __shared__ float sB[C];
    for (int t = threadIdx.x; t < C * CIN; t += blockDim.x) sWf[t] = g_Wf[t];
    for (int t = threadIdx.x; t < C; t += blockDim.x) sB[t] = g_bias[t];
    __syncthreads();

    int warp = threadIdx.x >> 5;
    int lane = threadIdx.x & 31;
    int s = blockIdx.x * 8 + warp;
    if (s >= s_count) return;

    const int c0 = lane, c1 = lane + 32;

    // pw1 rows for this lane's two output channels -> registers
    float w0[C], w1[C];
#pragma unroll
    for (int k = 0; k < C; k++) {
        w0[k] = __ldg(pw1 + c0 * C + k);
        w1[k] = __ldg(pw1 + c1 * C + k);
    }
    float wf0[CIN], wf1[CIN];
#pragma unroll
    for (int k = 0; k < CIN; k++) {
        wf0[k] = sWf[c0 * CIN + k];
        wf1[k] = sWf[c1 * CIN + k];
    }
    const float b0 = sB[c0], b1 = sB[c1];
    const float d0 = __ldg(dw1 + c0), d1 = __ldg(dw1 + c1);
    const float xg0 = g_xg[c0], xg1 = g_xg[c1];

    const int p0 = g_segstart[s];
    const int p1 = g_segstart[s + 1];

    float mx0 = -3.4e38f, mx1 = -3.4e38f;
    float sm0 = 0.0f, sm1 = 0.0f;

    for (int p = p0; p < p1; p++) {
        float raw = (lane < CIN) ? __ldg(inp + (size_t)p * CIN + lane) : 0.0f;
        float ink[CIN];
#pragma unroll
        for (int k = 0; k < CIN; k++) ink[k] = __shfl_sync(FULLMASK, raw, k);

        float x0 = b0, x1 = b1;
#pragma unroll
        for (int k = 0; k < CIN; k++) {
            x0 += wf0[k] * ink[k];
            x1 += wf1[k] * ink[k];
        }
        x0 = fmaxf(x0, 0.0f);
        x1 = fmaxf(x1, 0.0f);

        float s0 = x0 * d0, s1 = x1 * d1;
        float sw0 = s0 * sigmoidf_fast(s0);
        float sw1 = s1 * sigmoidf_fast(s1);

        float acc0 = xg0, acc1 = xg1;
#pragma unroll
        for (int k = 0; k < 32; k++) {
            float a = __shfl_sync(FULLMASK, sw0, k);   // sw for channel k
            float b = __shfl_sync(FULLMASK, sw1, k);   // sw for channel k+32
            acc0 += w0[k] * a;
            acc1 += w1[k] * a;
            acc0 += w0[k + 32] * b;
            acc1 += w1[k + 32] * b;
        }

        float wei0 = sigmoidf_fast(acc0);
        float wei1 = sigmoidf_fast(acc1);
        float xi0 = x0 * (1.0f + wei0);
        float xi1 = x1 * (1.0f + wei1);
        mx0 = fmaxf(mx0, xi0); sm0 += xi0;
        mx1 = fmaxf(mx1, xi1); sm1 += xi1;
    }

    out[(size_t)s * C + c0] = mx0 + sm0;
    out[(size_t)s * C + c1] = mx1 + sm1;
}

// ---------------- launch ----------------
extern "C" void kernel_launch(void* const* d_in, const int* in_sizes, int n_in,
                              void* d_out, int out_size) {
    const float* inp   = (const float*)d_in[0];
    const int*   unq   = (const int*)d_in[1];
    const float* W     = (const float*)d_in[2];
    const float* gamma = (const float*)d_in[3];
    const float* beta  = (const float*)d_in[4];
    const float* dw1   = (const float*)d_in[5];
    const float* pw1   = (const float*)d_in[6];
    const float* dw2   = (const float*)d_in[7];
    const float* pw2   = (const float*)d_in[8];
    float* out = (float*)d_out;

    int n = in_sizes[0] / CIN;     // 1,000,000
    int s = out_size / C;          // 30,000

    k_zero<<<1, 256>>>();
    k_bounds<<<(n + 255) / 256, 256>>>(unq, n, s);
    k_moments<<<592, 256>>>(inp, n);
    k_fold<<<1, 64>>>(W, gamma, beta, n);
    k_gpass<<<592, 256>>>(inp, n);
    k_xg<<<1, 64>>>(dw2, pw2, n);
    k_main<<<(s + 7) / 8, 256>>>(inp, pw1, dw1, out, s);
}

// round 5
// speedup vs baseline: 1.4823x; 1.4823x over previous
#include <cuda_runtime.h>
#include <cstdint>

#define CIN  10
#define C    64
#define SMAX 30001
#define NMAX 1000000
#define EPS  1e-3f
#define FULLMASK 0xffffffffu

// ---------------- device scratch (no allocations allowed) ----------------
__device__ float g_m1[CIN];         // sum of inputs per feature
__device__ float g_m2[55];          // upper-tri second moments
__device__ float g_Wf[C * CIN];     // BN-folded linear weights (scalar)
__device__ float g_bias[C];         // BN-folded bias (scalar)
__device__ float g_gsum[C];         // sum over points of relu(x)
__device__ float g_xg[C];           // global-branch additive term
__device__ int   g_segstart[SMAX];  // pillar start offsets (+ sentinel)
// packed (f32x2) parameter copies for the pipeline kernel
__device__ unsigned long long g_Wfp[32 * CIN];  // (Wf[2cp][k], Wf[2cp+1][k])
__device__ unsigned long long g_biasp[32];
__device__ unsigned long long g_dwp[32];
// per-point attention output xi [N][64]
__device__ float g_xi[(size_t)NMAX * C];

// ---------------- packed f32x2 helpers ----------------
__device__ __forceinline__ unsigned long long pack2(float lo, float hi) {
    unsigned long long r;
    asm("mov.b64 %0, {%1, %2};" : "=l"(r) : "f"(lo), "f"(hi));
    return r;
}
__device__ __forceinline__ void unpack2(unsigned long long v, float& lo, float& hi) {
    asm("mov.b64 {%0, %1}, %2;" : "=f"(lo), "=f"(hi) : "l"(v));
}
__device__ __forceinline__ unsigned long long fma2(unsigned long long a,
                                                   unsigned long long b,
                                                   unsigned long long c) {
    unsigned long long d;
    asm("fma.rn.f32x2 %0, %1, %2, %3;" : "=l"(d) : "l"(a), "l"(b), "l"(c));
    return d;
}
__device__ __forceinline__ unsigned long long mul2(unsigned long long a,
                                                   unsigned long long b) {
    unsigned long long d;
    asm("mul.rn.f32x2 %0, %1, %2;" : "=l"(d) : "l"(a), "l"(b));
    return d;
}
__device__ __forceinline__ unsigned long long add2(unsigned long long a,
                                                   unsigned long long b) {
    unsigned long long d;
    asm("add.rn.f32x2 %0, %1, %2;" : "=l"(d) : "l"(a), "l"(b));
    return d;
}

__device__ __forceinline__ float sigmoidf_fast(float z) {
    return __fdividef(1.0f, 1.0f + __expf(-z));
}
__device__ __forceinline__ float warp_sum(float v) {
#pragma unroll
    for (int o = 16; o > 0; o >>= 1) v += __shfl_down_sync(FULLMASK, v, o);
    return v;
}

// ---------------- K0: zero accumulators ----------------
__global__ void k_zero() {
    int t = threadIdx.x;
    if (t < CIN) g_m1[t] = 0.0f;
    if (t < 55)  g_m2[t] = 0.0f;
    if (t < C)   g_gsum[t] = 0.0f;
}

// ---------------- K1: segment boundaries (unq_inv sorted) ----------------
__global__ void k_bounds(const int* __restrict__ unq, int n, int s_count) {
    int i = blockIdx.x * blockDim.x + threadIdx.x;
    if (i >= n) return;
    int cur = unq[i];
    if (i == 0) {
        for (int t = 0; t <= cur; t++) g_segstart[t] = 0;
    } else {
        int prev = unq[i - 1];
        for (int t = prev + 1; t <= cur; t++) g_segstart[t] = i;
    }
    if (i == n - 1) {
        for (int t = cur + 1; t <= s_count; t++) g_segstart[t] = n;
    }
}

// ---------------- K2: input first/second moments ----------------
__global__ void k_moments(const float* __restrict__ inp, int n) {
    float a1[CIN];
    float a2[55];
#pragma unroll
    for (int k = 0; k < CIN; k++) a1[k] = 0.0f;
#pragma unroll
    for (int k = 0; k < 55; k++) a2[k] = 0.0f;

    int stride = gridDim.x * blockDim.x;
    for (int i = blockIdx.x * blockDim.x + threadIdx.x; i < n; i += stride) {
        const float* row = inp + (size_t)i * CIN;
        float v[CIN];
#pragma unroll
        for (int k = 0; k < CIN; k++) v[k] = __ldg(row + k);
        int t = 0;
#pragma unroll
        for (int j = 0; j < CIN; j++) {
            a1[j] += v[j];
#pragma unroll
            for (int k = j; k < CIN; k++) { a2[t] += v[j] * v[k]; t++; }
        }
    }

    int lane = threadIdx.x & 31;
#pragma unroll
    for (int j = 0; j < CIN; j++) {
        float r = warp_sum(a1[j]);
        if (lane == 0) atomicAdd(&g_m1[j], r);
    }
#pragma unroll
    for (int t = 0; t < 55; t++) {
        float r = warp_sum(a2[t]);
        if (lane == 0) atomicAdd(&g_m2[t], r);
    }
}

// ---------------- K3: fold BN into linear + build packed params ----------------
__global__ void k_fold(const float* __restrict__ W, const float* __restrict__ gamma,
                       const float* __restrict__ beta, const float* __restrict__ dw1,
                       int n) {
    int c = threadIdx.x;
    if (c < C) {
        float invn = 1.0f / (float)n;
        float wr[CIN];
#pragma unroll
        for (int k = 0; k < CIN; k++) wr[k] = W[c * CIN + k];

        float mu = 0.0f;
#pragma unroll
        for (int k = 0; k < CIN; k++) mu += wr[k] * g_m1[k];
        mu *= invn;

        float ex2 = 0.0f;
        int t = 0;
#pragma unroll
        for (int j = 0; j < CIN; j++) {
#pragma unroll
            for (int k = j; k < CIN; k++) {
                float f = wr[j] * wr[k] * g_m2[t];
                ex2 += (k == j) ? f : 2.0f * f;
                t++;
            }
        }
        ex2 *= invn;
        float var = ex2 - mu * mu;
        float alpha = gamma[c] * rsqrtf(var + EPS);
        g_bias[c] = beta[c] - mu * alpha;
#pragma unroll
        for (int k = 0; k < CIN; k++) g_Wf[c * CIN + k] = alpha * wr[k];
    }
    __syncthreads();
    // pack c-pairs for the f32x2 pipeline
    if (c < 32) {
#pragma unroll
        for (int k = 0; k < CIN; k++)
            g_Wfp[c * CIN + k] = pack2(g_Wf[(2 * c) * CIN + k],
                                       g_Wf[(2 * c + 1) * CIN + k]);
        g_biasp[c] = pack2(g_bias[2 * c], g_bias[2 * c + 1]);
        g_dwp[c]   = pack2(dw1[2 * c], dw1[2 * c + 1]);
    }
}

// ---------------- K4: accumulate g = sum over points of relu(x) ----------------
__global__ void k_gpass(const float* __restrict__ inp, int n) {
    __shared__ float sWf[C * CIN];
    __shared__ float sB[C];
    for (int t = threadIdx.x; t < C * CIN; t += blockDim.x) sWf[t] = g_Wf[t];
    for (int t = threadIdx.x; t < C; t += blockDim.x) sB[t] = g_bias[t];
    __syncthreads();

    float acc[C];
#pragma unroll
    for (int c = 0; c < C; c++) acc[c] = 0.0f;

    int stride = gridDim.x * blockDim.x;
    for (int i = blockIdx.x * blockDim.x + threadIdx.x; i < n; i += stride) {
        const float* row = inp + (size_t)i * CIN;
        float v[CIN];
#pragma unroll
        for (int k = 0; k < CIN; k++) v[k] = __ldg(row + k);
#pragma unroll
        for (int c = 0; c < C; c++) {
            float x = sB[c];
#pragma unroll
            for (int k = 0; k < CIN; k++) x += sWf[c * CIN + k] * v[k];
            acc[c] += fmaxf(x, 0.0f);
        }
    }

    int lane = threadIdx.x & 31;
#pragma unroll
    for (int c = 0; c < C; c++) {
        float r = warp_sum(acc[c]);
        if (lane == 0) atomicAdd(&g_gsum[c], r);
    }
}

// ---------------- K5: global branch xg = pw2 @ relu(dw2 * mean(x)) ----------------
__global__ void k_xg(const float* __restrict__ dw2, const float* __restrict__ pw2, int n) {
    __shared__ float t[C];
    int c = threadIdx.x;
    if (c < C) t[c] = fmaxf(dw2[c] * (g_gsum[c] / (float)n), 0.0f);
    __syncthreads();
    if (c >= C) return;
    float acc = 0.0f;
#pragma unroll
    for (int k = 0; k < C; k++) acc += pw2[c * C + k] * t[k];
    g_xg[c] = acc;
}

// ---------------- K6: point-parallel fused pipeline -> xi ----------------
#define VPAD 11
__global__ __launch_bounds__(128) void k_pipe(const float* __restrict__ inp,
                                              const float* __restrict__ pw1,
                                              int n) {
    __shared__ __align__(16) float s_pw1[C * C];                 // 16 KB
    __shared__ unsigned long long s_Wfp[32 * CIN];
    __shared__ unsigned long long s_bp[32];
    __shared__ unsigned long long s_dwp[32];
    __shared__ float s_xg[C];
    __shared__ float s_v[128 * VPAD];

    for (int t = threadIdx.x; t < C * C; t += 128) s_pw1[t] = pw1[t];
    for (int t = threadIdx.x; t < 32 * CIN; t += 128) s_Wfp[t] = g_Wfp[t];
    if (threadIdx.x < 32) {
        s_bp[threadIdx.x]  = g_biasp[threadIdx.x];
        s_dwp[threadIdx.x] = g_dwp[threadIdx.x];
    }
    if (threadIdx.x < C) s_xg[threadIdx.x] = g_xg[threadIdx.x];

    int base = blockIdx.x * 128;
    int cnt = n - base; if (cnt > 128) cnt = 128;
    // coalesced staging of point features
    for (int t = threadIdx.x; t < cnt * CIN; t += 128) {
        int r = t / CIN, k = t - r * CIN;
        s_v[r * VPAD + k] = inp[(size_t)base * CIN + t];
    }
    __syncthreads();

    int li = threadIdx.x;
    if (li >= cnt) return;

    // duplicated input pairs
    unsigned long long vd[CIN];
#pragma unroll
    for (int k = 0; k < CIN; k++) {
        float f = s_v[li * VPAD + k];
        vd[k] = pack2(f, f);
    }

    // x = relu(bn-folded linear), channel-pair packed
    unsigned long long xp[32];
#pragma unroll
    for (int cp = 0; cp < 32; cp++) {
        unsigned long long a = s_bp[cp];
#pragma unroll
        for (int k = 0; k < CIN; k++) a = fma2(s_Wfp[cp * CIN + k], vd[k], a);
        float lo, hi; unpack2(a, lo, hi);
        xp[cp] = pack2(fmaxf(lo, 0.0f), fmaxf(hi, 0.0f));
    }

    // sw = s * sigmoid(s), s = x * dw1, packed (pair = channels 2cp,2cp+1 = k-pairs)
    unsigned long long swp[32];
#pragma unroll
    for (int cp = 0; cp < 32; cp++) {
        unsigned long long sp = mul2(xp[cp], s_dwp[cp]);
        float a, b; unpack2(sp, a, b);
        swp[cp] = pack2(a * sigmoidf_fast(a), b * sigmoidf_fast(b));
    }

    // xl = pw1 @ sw + xg ; wei = sigmoid(xl) ; xi = x * (1 + wei)
    float* xiout = g_xi + (size_t)(base + li) * C;
    float ob[4];
#pragma unroll
    for (int c = 0; c < C; c++) {
        const ulonglong2* wr = reinterpret_cast<const ulonglong2*>(s_pw1 + c * C);
        unsigned long long a0 = 0ull, a1 = 0ull, a2 = 0ull, a3 = 0ull;
#pragma unroll
        for (int q = 0; q < 8; q++) {
            ulonglong2 w0 = wr[2 * q];
            ulonglong2 w1 = wr[2 * q + 1];
            a0 = fma2(w0.x, swp[4 * q + 0], a0);
            a1 = fma2(w0.y, swp[4 * q + 1], a1);
            a2 = fma2(w1.x, swp[4 * q + 2], a2);
            a3 = fma2(w1.y, swp[4 * q + 3], a3);
        }
        unsigned long long a = add2(add2(a0, a1), add2(a2, a3));
        float lo, hi; unpack2(a, lo, hi);
        float xl = lo + hi + s_xg[c];
        float wei = sigmoidf_fast(xl);
        float xlo, xhi; unpack2(xp[c >> 1], xlo, xhi);
        float xc = (c & 1) ? xhi : xlo;
        ob[c & 3] = xc * (1.0f + wei);
        if ((c & 3) == 3) {
            float4 o4 = make_float4(ob[0], ob[1], ob[2], ob[3]);
            *reinterpret_cast<float4*>(xiout + (c - 3)) = o4;
        }
    }
}

// ---------------- K7: segment reduce (max + sum), warp per pillar ----------------
__global__ __launch_bounds__(256) void k_reduce(float* __restrict__ out, int s_count) {
    int warp = threadIdx.x >> 5;
    int lane = threadIdx.x & 31;
    int s = blockIdx.x * 8 + warp;
    if (s >= s_count) return;
    int p0 = g_segstart[s];
    int p1 = g_segstart[s + 1];

    const float2* basep = reinterpret_cast<const float2*>(g_xi) + lane;
    float mx0 = -3.4e38f, mx1 = -3.4e38f, sm0 = 0.0f, sm1 = 0.0f;
    int p = p0;
    for (; p + 1 < p1; p += 2) {
        float2 v0 = __ldg(basep + (size_t)p * 32);
        float2 v1 = __ldg(basep + (size_t)(p + 1) * 32);
        mx0 = fmaxf(mx0, fmaxf(v0.x, v1.x)); sm0 += v0.x + v1.x;
        mx1 = fmaxf(mx1, fmaxf(v0.y, v1.y)); sm1 += v0.y + v1.y;
    }
    if (p < p1) {
        float2 v = __ldg(basep + (size_t)p * 32);
        mx0 = fmaxf(mx0, v.x); sm0 += v.x;
        mx1 = fmaxf(mx1, v.y); sm1 += v.y;
    }
    reinterpret_cast<float2*>(out)[(size_t)s * 32 + lane] =
        make_float2(mx0 + sm0, mx1 + sm1);
}

// ---------------- launch ----------------
extern "C" void kernel_launch(void* const* d_in, const int* in_sizes, int n_in,
                              void* d_out, int out_size) {
    const float* inp   = (const float*)d_in[0];
    const int*   unq   = (const int*)d_in[1];
    const float* W     = (const float*)d_in[2];
    const float* gamma = (const float*)d_in[3];
    const float* beta  = (const float*)d_in[4];
    const float* dw1   = (const float*)d_in[5];
    const float* pw1   = (const float*)d_in[6];
    const float* dw2   = (const float*)d_in[7];
    const float* pw2   = (const float*)d_in[8];
    float* out = (float*)d_out;

    int n = in_sizes[0] / CIN;     // 1,000,000
    int s = out_size / C;          // 30,000

    k_zero<<<1, 256>>>();
    k_bounds<<<(n + 255) / 256, 256>>>(unq, n, s);
    k_moments<<<592, 256>>>(inp, n);
    k_fold<<<1, 64>>>(W, gamma, beta, dw1, n);
    k_gpass<<<592, 256>>>(inp, n);
    k_xg<<<1, 64>>>(dw2, pw2, n);
    k_pipe<<<(n + 127) / 128, 128>>>(inp, pw1, n);
    k_reduce<<<(s + 7) / 8, 256>>>(out, s);
}

// round 7
// speedup vs baseline: 1.4882x; 1.0039x over previous
#include <cuda_runtime.h>
#include <cstdint>

#define CIN  10
#define C    64
#define SMAX 30001
#define NMAX 1000000
#define EPS  1e-3f
#define FULLMASK 0xffffffffu

typedef unsigned long long u64;

// ---------------- constant-memory parameter blocks ----------------
struct Params {
    u64   Wfp[32 * CIN];   // BN-folded linear weights, channel-pair packed
    u64   biasp[32];
    u64   dwp[32];
    float xg[C];
};
__device__   Params g_stage;          // staging (written by k_fold / k_xg)
__constant__ Params c_prm;            // copied in before k_pipe
__constant__ u64    c_pw1[32 * C];    // pw1 rows, adjacent-k pairs (raw 16KB copy)

// ---------------- device scratch ----------------
__device__ float g_m1[CIN];
__device__ float g_m2[55];
__device__ float g_Wf[C * CIN];
__device__ float g_bias[C];
__device__ float g_gsum[C];
__device__ int   g_segstart[SMAX];
__device__ float g_xi[(size_t)NMAX * C];

// ---------------- packed f32x2 helpers ----------------
__device__ __forceinline__ u64 pack2(float lo, float hi) {
    u64 r; asm("mov.b64 %0, {%1, %2};" : "=l"(r) : "f"(lo), "f"(hi)); return r;
}
__device__ __forceinline__ void unpack2(u64 v, float& lo, float& hi) {
    asm("mov.b64 {%0, %1}, %2;" : "=f"(lo), "=f"(hi) : "l"(v));
}
__device__ __forceinline__ u64 fma2(u64 a, u64 b, u64 c) {
    u64 d; asm("fma.rn.f32x2 %0, %1, %2, %3;" : "=l"(d) : "l"(a), "l"(b), "l"(c)); return d;
}
__device__ __forceinline__ u64 mul2(u64 a, u64 b) {
    u64 d; asm("mul.rn.f32x2 %0, %1, %2;" : "=l"(d) : "l"(a), "l"(b)); return d;
}
__device__ __forceinline__ u64 add2(u64 a, u64 b) {
    u64 d; asm("add.rn.f32x2 %0, %1, %2;" : "=l"(d) : "l"(a), "l"(b)); return d;
}

__device__ __forceinline__ float sigmoidf_fast(float z) {
    return __fdividef(1.0f, 1.0f + __expf(-z));
}
__device__ __forceinline__ float warp_sum(float v) {
#pragma unroll
    for (int o = 16; o > 0; o >>= 1) v += __shfl_down_sync(FULLMASK, v, o);
    return v;
}

// ---------------- K1: zero accumulators + segment boundaries ----------------
__global__ void k_bounds(const int* __restrict__ unq, int n, int s_count) {
    if (blockIdx.x == 0) {
        int t = threadIdx.x;
        if (t < CIN) g_m1[t] = 0.0f;
        if (t < 55)  g_m2[t] = 0.0f;
        if (t < C)   g_gsum[t] = 0.0f;
    }
    int i = blockIdx.x * blockDim.x + threadIdx.x;
    if (i >= n) return;
    int cur = unq[i];
    if (i == 0) {
        for (int t = 0; t <= cur; t++) g_segstart[t] = 0;
    } else {
        int prev = unq[i - 1];
        for (int t = prev + 1; t <= cur; t++) g_segstart[t] = i;
    }
    if (i == n - 1) {
        for (int t = cur + 1; t <= s_count; t++) g_segstart[t] = n;
    }
}

// ---------------- K2: input first/second moments ----------------
__global__ void k_moments(const float* __restrict__ inp, int n) {
    float a1[CIN];
    float a2[55];
#pragma unroll
    for (int k = 0; k < CIN; k++) a1[k] = 0.0f;
#pragma unroll
    for (int k = 0; k < 55; k++) a2[k] = 0.0f;

    int stride = gridDim.x * blockDim.x;
    for (int i = blockIdx.x * blockDim.x + threadIdx.x; i < n; i += stride) {
        const float* row = inp + (size_t)i * CIN;
        float v[CIN];
#pragma unroll
        for (int k = 0; k < CIN; k++) v[k] = __ldg(row + k);
        int t = 0;
#pragma unroll
        for (int j = 0; j < CIN; j++) {
            a1[j] += v[j];
#pragma unroll
            for (int k = j; k < CIN; k++) { a2[t] += v[j] * v[k]; t++; }
        }
    }

    int lane = threadIdx.x & 31;
#pragma unroll
    for (int j = 0; j < CIN; j++) {
        float r = warp_sum(a1[j]);
        if (lane == 0) atomicAdd(&g_m1[j], r);
    }
#pragma unroll
    for (int t = 0; t < 55; t++) {
        float r = warp_sum(a2[t]);
        if (lane == 0) atomicAdd(&g_m2[t], r);
    }
}

// ---------------- K3: fold BN into linear + stage packed params ----------------
__global__ void k_fold(const float* __restrict__ W, const float* __restrict__ gamma,
                       const float* __restrict__ beta, const float* __restrict__ dw1,
                       int n) {
    int c = threadIdx.x;
    if (c < C) {
        float invn = 1.0f / (float)n;
        float wr[CIN];
#pragma unroll
        for (int k = 0; k < CIN; k++) wr[k] = W[c * CIN + k];

        float mu = 0.0f;
#pragma unroll
        for (int k = 0; k < CIN; k++) mu += wr[k] * g_m1[k];
        mu *= invn;

        float ex2 = 0.0f;
        int t = 0;
#pragma unroll
        for (int j = 0; j < CIN; j++) {
#pragma unroll
            for (int k = j; k < CIN; k++) {
                float f = wr[j] * wr[k] * g_m2[t];
                ex2 += (k == j) ? f : 2.0f * f;
                t++;
            }
        }
        ex2 *= invn;
        float var = ex2 - mu * mu;
        float alpha = gamma[c] * rsqrtf(var + EPS);
        g_bias[c] = beta[c] - mu * alpha;
#pragma unroll
        for (int k = 0; k < CIN; k++) g_Wf[c * CIN + k] = alpha * wr[k];
    }
    __syncthreads();
    if (c < 32) {
#pragma unroll
        for (int k = 0; k < CIN; k++)
            g_stage.Wfp[c * CIN + k] = pack2(g_Wf[(2 * c) * CIN + k],
                                             g_Wf[(2 * c + 1) * CIN + k]);
        g_stage.biasp[c] = pack2(g_bias[2 * c], g_bias[2 * c + 1]);
        g_stage.dwp[c]   = pack2(dw1[2 * c], dw1[2 * c + 1]);
    }
}

// ---------------- K4: accumulate g = sum over points of relu(x) ----------------
__global__ void k_gpass(const float* __restrict__ inp, int n) {
    __shared__ float sWf[C * CIN];
    __shared__ float sB[C];
    for (int t = threadIdx.x; t < C * CIN; t += blockDim.x) sWf[t] = g_Wf[t];
    for (int t = threadIdx.x; t < C; t += blockDim.x) sB[t] = g_bias[t];
    __syncthreads();

    float acc[C];
#pragma unroll
    for (int c = 0; c < C; c++) acc[c] = 0.0f;

    int stride = gridDim.x * blockDim.x;
    for (int i = blockIdx.x * blockDim.x + threadIdx.x; i < n; i += stride) {
        const float* row = inp + (size_t)i * CIN;
        float v[CIN];
#pragma unroll
        for (int k = 0; k < CIN; k++) v[k] = __ldg(row + k);
#pragma unroll
        for (int c = 0; c < C; c++) {
            float x = sB[c];
#pragma unroll
            for (int k = 0; k < CIN; k++) x += sWf[c * CIN + k] * v[k];
            acc[c] += fmaxf(x, 0.0f);
        }
    }

    int lane = threadIdx.x & 31;
#pragma unroll
    for (int c = 0; c < C; c++) {
        float r = warp_sum(acc[c]);
        if (lane == 0) atomicAdd(&g_gsum[c], r);
    }
}

// ---------------- K5: global branch -> stage xg ----------------
__global__ void k_xg(const float* __restrict__ dw2, const float* __restrict__ pw2, int n) {
    __shared__ float t[C];
    int c = threadIdx.x;
    if (c < C) t[c] = fmaxf(dw2[c] * (g_gsum[c] / (float)n), 0.0f);
    __syncthreads();
    if (c >= C) return;
    float acc = 0.0f;
#pragma unroll
    for (int k = 0; k < C; k++) acc += pw2[c * C + k] * t[k];
    g_stage.xg[c] = acc;
}

// ---------------- K6: point-parallel fused pipeline -> xi ----------------
__global__ __launch_bounds__(128) void k_pipe(const float* __restrict__ inp, int n) {
    __shared__ float x_s[128 * 65];   // 33.3 KB, per-point row stride 65 (conflict-free)

    int li = threadIdx.x;
    int base = blockIdx.x * 128;
    int cnt = n - base; if (cnt > 128) cnt = 128;

    if (li < cnt) {
        const float* row = inp + (size_t)(base + li) * CIN;
        u64 vd[CIN];
#pragma unroll
        for (int k = 0; k < CIN; k++) {
            float f = __ldg(row + k);
            vd[k] = pack2(f, f);
        }

        float* xr = x_s + li * 65;
        u64 swp[32];

        // phase A: x = relu(folded linear); store x to shared; sw = s*sigmoid(s)
#pragma unroll
        for (int cp = 0; cp < 32; cp++) {
            u64 a = c_prm.biasp[cp];
#pragma unroll
            for (int k = 0; k < CIN; k++) a = fma2(c_prm.Wfp[cp * CIN + k], vd[k], a);
            float lo, hi; unpack2(a, lo, hi);
            lo = fmaxf(lo, 0.0f); hi = fmaxf(hi, 0.0f);
            xr[2 * cp]     = lo;
            xr[2 * cp + 1] = hi;
            u64 sp = mul2(pack2(lo, hi), c_prm.dwp[cp]);
            float sa, sb; unpack2(sp, sa, sb);
            swp[cp] = pack2(sa * sigmoidf_fast(sa), sb * sigmoidf_fast(sb));
        }

        // phase B: xl = pw1 @ sw + xg ; xi = x*(1+sigmoid(xl)) in-place in shared
#pragma unroll 4
        for (int c = 0; c < C; c++) {
            const u64* wr = c_pw1 + c * 32;
            u64 a0 = 0ull, a1 = 0ull, a2 = 0ull, a3 = 0ull;
#pragma unroll
            for (int q = 0; q < 8; q++) {
                a0 = fma2(wr[4 * q + 0], swp[4 * q + 0], a0);
                a1 = fma2(wr[4 * q + 1], swp[4 * q + 1], a1);
                a2 = fma2(wr[4 * q + 2], swp[4 * q + 2], a2);
                a3 = fma2(wr[4 * q + 3], swp[4 * q + 3], a3);
            }
            u64 a = add2(add2(a0, a1), add2(a2, a3));
            float lo, hi; unpack2(a, lo, hi);
            float wei = sigmoidf_fast(lo + hi + c_prm.xg[c]);
            xr[c] *= (1.0f + wei);
        }
    }
    __syncthreads();

    // phase C: coalesced write-out of the block's xi tile
    float* xiout = g_xi + (size_t)base * C;
    int tot = cnt * C;
    for (int t = li; t < tot; t += 128) {
        int r = t >> 6, cc = t & 63;
        xiout[t] = x_s[r * 65 + cc];
    }
}

// ---------------- K7: segment reduce (max + sum), warp per pillar ----------------
__global__ __launch_bounds__(256) void k_reduce(float* __restrict__ out, int s_count) {
    int warp = threadIdx.x >> 5;
    int lane = threadIdx.x & 31;
    int s = blockIdx.x * 8 + warp;
    if (s >= s_count) return;
    int p0 = g_segstart[s];
    int p1 = g_segstart[s + 1];

    const float2* basep = reinterpret_cast<const float2*>(g_xi) + lane;
    float mx0 = -3.4e38f, mx1 = -3.4e38f, sm0 = 0.0f, sm1 = 0.0f;
    int p = p0;
    for (; p + 1 < p1; p += 2) {
        float2 v0 = __ldg(basep + (size_t)p * 32);
        float2 v1 = __ldg(basep + (size_t)(p + 1) * 32);
        mx0 = fmaxf(mx0, fmaxf(v0.x, v1.x)); sm0 += v0.x + v1.x;
        mx1 = fmaxf(mx1, fmaxf(v0.y, v1.y)); sm1 += v0.y + v1.y;
    }
    if (p < p1) {
        float2 v = __ldg(basep + (size_t)p * 32);
        mx0 = fmaxf(mx0, v.x); sm0 += v.x;
        mx1 = fmaxf(mx1, v.y); sm1 += v.y;
    }
    reinterpret_cast<float2*>(out)[(size_t)s * 32 + lane] =
        make_float2(mx0 + sm0, mx1 + sm1);
}

// ---------------- launch ----------------
extern "C" void kernel_launch(void* const* d_in, const int* in_sizes, int n_in,
                              void* d_out, int out_size) {
    const float* inp   = (const float*)d_in[0];
    const int*   unq   = (const int*)d_in[1];
    const float* W     = (const float*)d_in[2];
    const float* gamma = (const float*)d_in[3];
    const float* beta  = (const float*)d_in[4];
    const float* dw1   = (const float*)d_in[5];
    const float* pw1   = (const float*)d_in[6];
    const float* dw2   = (const float*)d_in[7];
    const float* pw2   = (const float*)d_in[8];
    float* out = (float*)d_out;

    int n = in_sizes[0] / CIN;     // 1,000,000
    int s = out_size / C;          // 30,000

    // raw pw1 -> constant (adjacent-k float pairs == u64 lanes), D2D async copy
    cudaMemcpyToSymbolAsync(c_pw1, pw1, 32 * C * sizeof(u64), 0,
                            cudaMemcpyDeviceToDevice, 0);

    k_bounds<<<(n + 255) / 256, 256>>>(unq, n, s);              // launch 1
    k_moments<<<592, 256>>>(inp, n);                            // launch 2
    k_fold<<<1, 64>>>(W, gamma, beta, dw1, n);                  // launch 3
    k_gpass<<<592, 256>>>(inp, n);                              // launch 4
    k_xg<<<1, 64>>>(dw2, pw2, n);                               // launch 5

    // staged folded params -> constant
    void* stage_ptr = nullptr;
    cudaGetSymbolAddress(&stage_ptr, g_stage);
    cudaMemcpyToSymbolAsync(c_prm, stage_ptr, sizeof(Params), 0,
                            cudaMemcpyDeviceToDevice, 0);

    k_pipe<<<(n + 127) / 128, 128>>>(inp, n);                   // launch 6 (profiled)
    k_reduce<<<(s + 7) / 8, 256>>>(out, s);                     // launch 7
}

// round 8
// speedup vs baseline: 2.0790x; 1.3970x over previous
#include <cuda_runtime.h>
#include <cstdint>

#define CIN  10
#define C    64
#define SMAX 30001
#define EPS  1e-3f
#define FULLMASK 0xffffffffu

typedef unsigned long long u64;

// ---------------- parameter staging (read by k_pipe into shared) ----------------
struct Params {
    u64   Wfp[32 * CIN];   // BN-folded linear weights, channel-pair packed
    u64   biasp[32];
    u64   dwp[32];
    float xg[C];
};
__device__ Params g_stage;

// ---------------- device scratch ----------------
__device__ float g_m1[CIN];
__device__ float g_m2[55];
__device__ float g_Wf[C * CIN];
__device__ float g_bias[C];
__device__ float g_gsum[C];
__device__ int   g_segstart[SMAX];
// per-pillar partials, 2 slots (pillar-start subtile / spill subtile)
__device__ float g_pmax[(size_t)2 * SMAX * C];
__device__ float g_psum[(size_t)2 * SMAX * C];

// ---------------- packed f32x2 helpers ----------------
__device__ __forceinline__ u64 pack2(float lo, float hi) {
    u64 r; asm("mov.b64 %0, {%1, %2};" : "=l"(r) : "f"(lo), "f"(hi)); return r;
}
__device__ __forceinline__ void unpack2(u64 v, float& lo, float& hi) {
    asm("mov.b64 {%0, %1}, %2;" : "=f"(lo), "=f"(hi) : "l"(v));
}
__device__ __forceinline__ u64 fma2(u64 a, u64 b, u64 c) {
    u64 d; asm("fma.rn.f32x2 %0, %1, %2, %3;" : "=l"(d) : "l"(a), "l"(b), "l"(c)); return d;
}
__device__ __forceinline__ u64 mul2(u64 a, u64 b) {
    u64 d; asm("mul.rn.f32x2 %0, %1, %2;" : "=l"(d) : "l"(a), "l"(b)); return d;
}
__device__ __forceinline__ u64 add2(u64 a, u64 b) {
    u64 d; asm("add.rn.f32x2 %0, %1, %2;" : "=l"(d) : "l"(a), "l"(b)); return d;
}

__device__ __forceinline__ float sigmoidf_fast(float z) {
    return __fdividef(1.0f, 1.0f + __expf(-z));
}
__device__ __forceinline__ float warp_sum(float v) {
#pragma unroll
    for (int o = 16; o > 0; o >>= 1) v += __shfl_down_sync(FULLMASK, v, o);
    return v;
}

// ---------------- K1: zero accumulators + segment boundaries ----------------
__global__ void k_bounds(const int* __restrict__ unq, int n, int s_count) {
    if (blockIdx.x == 0) {
        int t = threadIdx.x;
        if (t < CIN) g_m1[t] = 0.0f;
        if (t < 55)  g_m2[t] = 0.0f;
        if (t < C)   g_gsum[t] = 0.0f;
    }
    int i = blockIdx.x * blockDim.x + threadIdx.x;
    if (i >= n) return;
    int cur = unq[i];
    if (i == 0) {
        for (int t = 0; t <= cur; t++) g_segstart[t] = 0;
    } else {
        int prev = unq[i - 1];
        for (int t = prev + 1; t <= cur; t++) g_segstart[t] = i;
    }
    if (i == n - 1) {
        for (int t = cur + 1; t <= s_count; t++) g_segstart[t] = n;
    }
}

// ---------------- K2: input first/second moments ----------------
__global__ void k_moments(const float* __restrict__ inp, int n) {
    float a1[CIN];
    float a2[55];
#pragma unroll
    for (int k = 0; k < CIN; k++) a1[k] = 0.0f;
#pragma unroll
    for (int k = 0; k < 55; k++) a2[k] = 0.0f;

    int stride = gridDim.x * blockDim.x;
    for (int i = blockIdx.x * blockDim.x + threadIdx.x; i < n; i += stride) {
        const float* row = inp + (size_t)i * CIN;
        float v[CIN];
#pragma unroll
        for (int k = 0; k < CIN; k++) v[k] = __ldg(row + k);
        int t = 0;
#pragma unroll
        for (int j = 0; j < CIN; j++) {
            a1[j] += v[j];
#pragma unroll
            for (int k = j; k < CIN; k++) { a2[t] += v[j] * v[k]; t++; }
        }
    }

    int lane = threadIdx.x & 31;
#pragma unroll
    for (int j = 0; j < CIN; j++) {
        float r = warp_sum(a1[j]);
        if (lane == 0) atomicAdd(&g_m1[j], r);
    }
#pragma unroll
    for (int t = 0; t < 55; t++) {
        float r = warp_sum(a2[t]);
        if (lane == 0) atomicAdd(&g_m2[t], r);
    }
}

// ---------------- K3: fold BN into linear + stage packed params ----------------
__global__ void k_fold(const float* __restrict__ W, const float* __restrict__ gamma,
                       const float* __restrict__ beta, const float* __restrict__ dw1,
                       int n) {
    int c = threadIdx.x;
    if (c < C) {
        float invn = 1.0f / (float)n;
        float wr[CIN];
#pragma unroll
        for (int k = 0; k < CIN; k++) wr[k] = W[c * CIN + k];

        float mu = 0.0f;
#pragma unroll
        for (int k = 0; k < CIN; k++) mu += wr[k] * g_m1[k];
        mu *= invn;

        float ex2 = 0.0f;
        int t = 0;
#pragma unroll
        for (int j = 0; j < CIN; j++) {
#pragma unroll
            for (int k = j; k < CIN; k++) {
                float f = wr[j] * wr[k] * g_m2[t];
                ex2 += (k == j) ? f : 2.0f * f;
                t++;
            }
        }
        ex2 *= invn;
        float var = ex2 - mu * mu;
        float alpha = gamma[c] * rsqrtf(var + EPS);
        g_bias[c] = beta[c] - mu * alpha;
#pragma unroll
        for (int k = 0; k < CIN; k++) g_Wf[c * CIN + k] = alpha * wr[k];
    }
    __syncthreads();
    if (c < 32) {
#pragma unroll
        for (int k = 0; k < CIN; k++)
            g_stage.Wfp[c * CIN + k] = pack2(g_Wf[(2 * c) * CIN + k],
                                             g_Wf[(2 * c + 1) * CIN + k]);
        g_stage.biasp[c] = pack2(g_bias[2 * c], g_bias[2 * c + 1]);
        g_stage.dwp[c]   = pack2(dw1[2 * c], dw1[2 * c + 1]);
    }
}

// ---------------- K4: g = sum over points of relu(x), channel-per-thread ----------------
#define GP_TILE 256
__global__ __launch_bounds__(256) void k_gpass(const float* __restrict__ inp, int n) {
    __shared__ __align__(16) float s_v[GP_TILE * 12];
    __shared__ float s_acc[C];

    int t = threadIdx.x;
    int c = t & 63, g = t >> 6;

    float w[CIN];
#pragma unroll
    for (int k = 0; k < CIN; k++) w[k] = g_Wf[c * CIN + k];
    float b = g_bias[c];
    if (t < C) s_acc[t] = 0.0f;

    float acc = 0.0f;
    for (int base = blockIdx.x * GP_TILE; base < n; base += gridDim.x * GP_TILE) {
        int cnt = n - base; if (cnt > GP_TILE) cnt = GP_TILE;
        __syncthreads();
        for (int i = t; i < cnt * CIN; i += 256) {
            int r = i / CIN, k = i - r * CIN;
            s_v[r * 12 + k] = inp[(size_t)base * CIN + i];
        }
        __syncthreads();
        int p0 = g * 64, p1 = p0 + 64; if (p1 > cnt) p1 = cnt;
        for (int p = p0; p < p1; p++) {
            const float* vr = s_v + p * 12;
            float4 va = *reinterpret_cast<const float4*>(vr);
            float4 vb = *reinterpret_cast<const float4*>(vr + 4);
            float2 vc = *reinterpret_cast<const float2*>(vr + 8);
            float x = b;
            x += w[0] * va.x; x += w[1] * va.y; x += w[2] * va.z; x += w[3] * va.w;
            x += w[4] * vb.x; x += w[5] * vb.y; x += w[6] * vb.z; x += w[7] * vb.w;
            x += w[8] * vc.x; x += w[9] * vc.y;
            acc += fmaxf(x, 0.0f);
        }
    }
    atomicAdd(&s_acc[c], acc);
    __syncthreads();
    if (t < C) atomicAdd(&g_gsum[t], s_acc[t]);
}

// ---------------- K5: global branch -> stage xg ----------------
__global__ void k_xg(const float* __restrict__ dw2, const float* __restrict__ pw2, int n) {
    __shared__ float t[C];
    int c = threadIdx.x;
    if (c < C) t[c] = fmaxf(dw2[c] * (g_gsum[c] / (float)n), 0.0f);
    __syncthreads();
    if (c >= C) return;
    float acc = 0.0f;
#pragma unroll
    for (int k = 0; k < C; k++) acc += pw2[c * C + k] * t[k];
    g_stage.xg[c] = acc;
}

// ---------------- K6: fused pipeline + in-block segment partials ----------------
// dynamic shared layout (bytes):
//   x_s    [128*65 f32]  @ 0       (33280)
//   s_pw1  [32*C u64]    @ 33280   (16384)
//   s_Wfp  [32*CIN u64]  @ 49664   (2560)
//   s_bp   [32 u64]      @ 52224   (256)
//   s_dwp  [32 u64]      @ 52480   (256)
//   s_u    [128 int]     @ 52736   (512)
//   s_xg   [C f32]       @ 53248   (256)
#define PIPE_SMEM 53504
__global__ __launch_bounds__(128) void k_pipe(const float* __restrict__ inp,
                                              const float* __restrict__ pw1,
                                              const int* __restrict__ unq,
                                              int n) {
    extern __shared__ __align__(16) char dsm[];
    float* x_s   = reinterpret_cast<float*>(dsm);
    u64*   s_pw1 = reinterpret_cast<u64*>(dsm + 33280);
    u64*   s_Wfp = reinterpret_cast<u64*>(dsm + 49664);
    u64*   s_bp  = reinterpret_cast<u64*>(dsm + 52224);
    u64*   s_dwp = reinterpret_cast<u64*>(dsm + 52480);
    int*   s_u   = reinterpret_cast<int*>(dsm + 52736);
    float* s_xg  = reinterpret_cast<float*>(dsm + 53248);

    int li = threadIdx.x;
    int base = blockIdx.x * 128;
    int cnt = n - base; if (cnt > 128) cnt = 128;

    // cooperative parameter loads
    const u64* pw1u = reinterpret_cast<const u64*>(pw1);
    for (int t = li; t < 32 * C; t += 128) s_pw1[t] = __ldg(pw1u + t);
    for (int t = li; t < 32 * CIN; t += 128) s_Wfp[t] = g_stage.Wfp[t];
    if (li < 32) { s_bp[li] = g_stage.biasp[li]; s_dwp[li] = g_stage.dwp[li]; }
    if (li < C) s_xg[li] = g_stage.xg[li];
    if (li < cnt) s_u[li] = __ldg(unq + base + li);
    __syncthreads();

    if (li < cnt) {
        const float* row = inp + (size_t)(base + li) * CIN;
        u64 vd[CIN];
#pragma unroll
        for (int k = 0; k < CIN; k++) {
            float f = __ldg(row + k);
            vd[k] = pack2(f, f);
        }

        float* xr = x_s + li * 65;
        u64 swp[32];

        // phase A: x = relu(folded linear) -> shared; sw = s*sigmoid(s)
#pragma unroll
        for (int cp = 0; cp < 32; cp++) {
            u64 a = s_bp[cp];
#pragma unroll
            for (int k = 0; k < CIN; k++) a = fma2(s_Wfp[cp * CIN + k], vd[k], a);
            float lo, hi; unpack2(a, lo, hi);
            lo = fmaxf(lo, 0.0f); hi = fmaxf(hi, 0.0f);
            xr[2 * cp]     = lo;
            xr[2 * cp + 1] = hi;
            u64 sp = mul2(pack2(lo, hi), s_dwp[cp]);
            float sa, sb; unpack2(sp, sa, sb);
            swp[cp] = pack2(sa * sigmoidf_fast(sa), sb * sigmoidf_fast(sb));
        }

        // phase B: xl = pw1 @ sw + xg ; xi = x*(1+sigmoid(xl)) in-place
#pragma unroll 4
        for (int c = 0; c < C; c++) {
            const ulonglong2* wv = reinterpret_cast<const ulonglong2*>(s_pw1 + c * 32);
            u64 a0 = 0ull, a1 = 0ull, a2 = 0ull, a3 = 0ull;
#pragma unroll
            for (int q = 0; q < 8; q++) {
                ulonglong2 w01 = wv[2 * q];
                ulonglong2 w23 = wv[2 * q + 1];
                a0 = fma2(w01.x, swp[4 * q + 0], a0);
                a1 = fma2(w01.y, swp[4 * q + 1], a1);
                a2 = fma2(w23.x, swp[4 * q + 2], a2);
                a3 = fma2(w23.y, swp[4 * q + 3], a3);
            }
            u64 a = add2(add2(a0, a1), add2(a2, a3));
            float lo, hi; unpack2(a, lo, hi);
            float wei = sigmoidf_fast(lo + hi + s_xg[c]);
            xr[c] *= (1.0f + wei);
        }
    }
    __syncthreads();

    // phase C: per-pillar partial (max,sum) per 64-pt subtile -> 2-slot scratch
    {
        int h = li >> 6, c = li & 63;
        int p = h * 64, pend = p + 64; if (pend > cnt) pend = cnt;
        if (p < pend) {
            int mytile = (base >> 6) + h;
            int cur = s_u[p];
            float v = x_s[p * 65 + c];
            float mx = v, sm = v;
            for (p++; p < pend; p++) {
                int u = s_u[p];
                float w = x_s[p * 65 + c];
                if (u != cur) {
                    size_t slot = ((g_segstart[cur] >> 6) == mytile) ? 0 : 1;
                    size_t idx = slot * ((size_t)SMAX * C) + (size_t)cur * C + c;
                    g_pmax[idx] = mx;
                    g_psum[idx] = sm;
                    cur = u; mx = w; sm = w;
                } else {
                    mx = fmaxf(mx, w); sm += w;
                }
            }
            size_t slot = ((g_segstart[cur] >> 6) == mytile) ? 0 : 1;
            size_t idx = slot * ((size_t)SMAX * C) + (size_t)cur * C + c;
            g_pmax[idx] = mx;
            g_psum[idx] = sm;
        }
    }
}

// ---------------- K7: combine per-pillar partials -> out ----------------
__global__ __launch_bounds__(256) void k_combine(float* __restrict__ out, int s_count) {
    int s = blockIdx.x * 8 + (threadIdx.x >> 5);
    int lane = threadIdx.x & 31;
    if (s >= s_count) return;
    int p0 = g_segstart[s], p1 = g_segstart[s + 1];
    size_t i0 = (size_t)s * C + 2 * lane;
    if (p1 <= p0) {  // empty segment (shouldn't occur): neutral output
        out[i0] = 0.0f; out[i0 + 1] = 0.0f;
        return;
    }
    float2 m = *reinterpret_cast<const float2*>(g_pmax + i0);
    float2 q = *reinterpret_cast<const float2*>(g_psum + i0);
    if (((p1 - 1) >> 6) > (p0 >> 6)) {
        size_t i1 = (size_t)SMAX * C + i0;
        float2 m1 = *reinterpret_cast<const float2*>(g_pmax + i1);
        float2 q1 = *reinterpret_cast<const float2*>(g_psum + i1);
        m.x = fmaxf(m.x, m1.x); m.y = fmaxf(m.y, m1.y);
        q.x += q1.x; q.y += q1.y;
    }
    *reinterpret_cast<float2*>(out + i0) = make_float2(m.x + q.x, m.y + q.y);
}

// ---------------- launch ----------------
extern "C" void kernel_launch(void* const* d_in, const int* in_sizes, int n_in,
                              void* d_out, int out_size) {
    const float* inp   = (const float*)d_in[0];
    const int*   unq   = (const int*)d_in[1];
    const float* W     = (const float*)d_in[2];
    const float* gamma = (const float*)d_in[3];
    const float* beta  = (const float*)d_in[4];
    const float* dw1   = (const float*)d_in[5];
    const float* pw1   = (const float*)d_in[6];
    const float* dw2   = (const float*)d_in[7];
    const float* pw2   = (const float*)d_in[8];
    float* out = (float*)d_out;

    int n = in_sizes[0] / CIN;     // 1,000,000
    int s = out_size / C;          // 30,000

    static bool attr_done = false;
    if (!attr_done) {
        cudaFuncSetAttribute(k_pipe, cudaFuncAttributeMaxDynamicSharedMemorySize,
                             PIPE_SMEM);
        attr_done = true;
    }

    k_bounds<<<(n + 255) / 256, 256>>>(unq, n, s);                 // launch 1
    k_moments<<<592, 256>>>(inp, n);                               // launch 2
    k_fold<<<1, 64>>>(W, gamma, beta, dw1, n);                     // launch 3
    k_gpass<<<592, 256>>>(inp, n);                                 // launch 4
    k_xg<<<1, 64>>>(dw2, pw2, n);                                  // launch 5
    k_pipe<<<(n + 127) / 128, 128, PIPE_SMEM>>>(inp, pw1, unq, n); // launch 6 (profiled)
    k_combine<<<(s + 7) / 8, 256>>>(out, s);                       // launch 7
}